// round 4
// baseline (speedup 1.0000x reference)
#include <cuda_runtime.h>

#define B_DIM 4
#define C_DIM 2
#define E_DIM 256
#define L_DIM 16000
#define W_DIM 40
#define STEP  20
#define T_DIM ((L_DIM - 1) * STEP + W_DIM)   // 320020
#define NT    128
#define EUNR  4
#define BLOCKS_PER_BC (L_DIM / NT)           // 125
#define OUT_ELEMS (B_DIM * C_DIM * T_DIM)    // 2560160

// Transposed basis, packed as float4: cbasis[e*10+q] = basis[4q..4q+3][e]
__constant__ float4 cbasis[E_DIM * 10];
__device__ float4 g_basis_scratch[E_DIM * 10];

// ---------- packed f32x2 helpers ----------
__device__ __forceinline__ unsigned long long pack2(float lo, float hi) {
    unsigned long long r;
    asm("mov.b64 %0, {%1, %2};" : "=l"(r) : "f"(lo), "f"(hi));
    return r;
}
__device__ __forceinline__ void unpack2(unsigned long long v, float& lo, float& hi) {
    asm("mov.b64 {%0, %1}, %2;" : "=f"(lo), "=f"(hi) : "l"(v));
}
__device__ __forceinline__ void fma2(unsigned long long& acc,
                                     unsigned long long a, unsigned long long b) {
    asm("fma.rn.f32x2 %0, %1, %2, %0;" : "+l"(acc) : "l"(a), "l"(b));
}

// ---------- prep: zero output AND transpose basis in one launch ----------
__global__ void prep_kernel(const float* __restrict__ basis,
                            float4* __restrict__ out4, int n4) {
    int i = blockIdx.x * blockDim.x + threadIdx.x;
    if (i < n4) out4[i] = make_float4(0.f, 0.f, 0.f, 0.f);
    if (i < E_DIM * 10) {
        int e = i / 10, q = i - e * 10;
        float4 v;
        v.x = basis[(4 * q + 0) * E_DIM + e];
        v.y = basis[(4 * q + 1) * E_DIM + e];
        v.z = basis[(4 * q + 2) * E_DIM + e];
        v.w = basis[(4 * q + 3) * E_DIM + e];
        g_basis_scratch[i] = v;
    }
}

__global__ void __launch_bounds__(NT, 8)
decoder_kernel(const float* __restrict__ mix,
               const float* __restrict__ mask,
               float* __restrict__ out) {
    // block -> (b, c, 128-chunk of l); threads -> consecutive l (coalesced)
    const int bc  = blockIdx.x / BLOCKS_PER_BC;          // 0..7
    const int blk = blockIdx.x - bc * BLOCKS_PER_BC;
    const int b   = bc >> 1;
    const int c   = bc & 1;
    const int l   = blk * NT + threadIdx.x;
    const int lane = threadIdx.x & 31;

    const float* pm = mix  + (size_t)b * E_DIM * L_DIM + l;
    const float* pk = mask + ((size_t)b * C_DIM + c) * E_DIM * L_DIM + l;

    unsigned long long acc[20];
#pragma unroll
    for (int i = 0; i < 20; ++i) acc[i] = 0ull;

#pragma unroll 1
    for (int e = 0; e < E_DIM; e += EUNR) {
        // front-batched loads: 8 independent LDGs in flight
        float m[EUNR], kv[EUNR];
#pragma unroll
        for (int u = 0; u < EUNR; ++u) m[u]  = pm[(size_t)u * L_DIM];
#pragma unroll
        for (int u = 0; u < EUNR; ++u) kv[u] = pk[(size_t)u * L_DIM];
        pm += (size_t)EUNR * L_DIM;
        pk += (size_t)EUNR * L_DIM;

#pragma unroll
        for (int u = 0; u < EUNR; ++u) {
            float s = m[u] * kv[u];
            unsigned long long sd = pack2(s, s);
            // basis row from __constant__, index (e+u) is warp-uniform -> LDCU
            const float4* brow = &cbasis[(e + u) * 10];
#pragma unroll
            for (int q = 0; q < 10; ++q) {
                float4 bv = brow[q];
                fma2(acc[2 * q],     sd, pack2(bv.x, bv.y));
                fma2(acc[2 * q + 1], sd, pack2(bv.z, bv.w));
            }
        }
    }

    // ---------- fused overlap-add epilogue ----------
    float f[W_DIM];
#pragma unroll
    for (int q = 0; q < 20; ++q) unpack2(acc[q], f[2 * q], f[2 * q + 1]);

    const size_t base = (size_t)bc * T_DIM + (size_t)l * STEP;
    // segment l = frame[l][0:20] + frame[l-1][20:40] (prev frame via shuffle)
#pragma unroll
    for (int j = 0; j < STEP; ++j) {
        float up = __shfl_up_sync(0xffffffffu, f[STEP + j], 1);
        float lo = f[j];
        if (lane > 0)      out[base + j] = lo + up;          // complete value
        else if (l > 0)    atomicAdd(&out[base + j], lo);    // pairs with prev warp
        else               out[base + j] = lo;               // l==0: sole contributor
    }
    if (lane == 31) {
#pragma unroll
        for (int j = 0; j < STEP; ++j)
            atomicAdd(&out[base + STEP + j], f[STEP + j]);
    }
}

extern "C" void kernel_launch(void* const* d_in, const int* in_sizes, int n_in,
                              void* d_out, int out_size) {
    // Identify inputs by element count for robustness.
    const float *mix = nullptr, *mask = nullptr, *basis = nullptr;
    for (int i = 0; i < n_in; ++i) {
        long long s = in_sizes[i];
        if (s == (long long)B_DIM * E_DIM * L_DIM)              mix   = (const float*)d_in[i];
        else if (s == (long long)B_DIM * C_DIM * E_DIM * L_DIM) mask  = (const float*)d_in[i];
        else if (s == (long long)W_DIM * E_DIM)                 basis = (const float*)d_in[i];
    }
    float* out = (float*)d_out;

    // 1) zero output + transpose basis (one launch)
    int n4 = out_size / 4;
    prep_kernel<<<(n4 + 255) / 256, 256>>>(basis, (float4*)out, n4);

    // 2) scratch -> __constant__ (async D2D memcpy node; graph-capturable)
    void* scratch_ptr = nullptr;
    cudaGetSymbolAddress(&scratch_ptr, g_basis_scratch);
    cudaMemcpyToSymbolAsync(cbasis, scratch_ptr, E_DIM * 10 * sizeof(float4), 0,
                            cudaMemcpyDeviceToDevice, 0);

    // 3) main kernel: one thread per (b,c,l)
    decoder_kernel<<<B_DIM * C_DIM * BLOCKS_PER_BC, NT>>>(mix, mask, out);
}

// round 5
// speedup vs baseline: 1.2899x; 1.2899x over previous
#include <cuda_runtime.h>

#define B_DIM 4
#define C_DIM 2
#define E_DIM 256
#define L_DIM 16000
#define W_DIM 40
#define STEP  20
#define T_DIM ((L_DIM - 1) * STEP + W_DIM)   // 320020
#define NT    128
#define EUNR  4

// ---------- packed f32x2 helpers ----------
__device__ __forceinline__ unsigned long long pack2(float lo, float hi) {
    unsigned long long r;
    asm("mov.b64 %0, {%1, %2};" : "=l"(r) : "f"(lo), "f"(hi));
    return r;
}
__device__ __forceinline__ void unpack2(unsigned long long v, float& lo, float& hi) {
    asm("mov.b64 {%0, %1}, %2;" : "=f"(lo), "=f"(hi) : "l"(v));
}
__device__ __forceinline__ void fma2(unsigned long long& acc,
                                     unsigned long long a, unsigned long long b) {
    asm("fma.rn.f32x2 %0, %1, %2, %0;" : "+l"(acc) : "l"(a), "l"(b));
}

// ---------- zero-init (d_out is poisoned; atomic targets need 0) ----------
__global__ void zero_kernel(float4* __restrict__ out, int n4) {
    int i = blockIdx.x * blockDim.x + threadIdx.x;
    if (i < n4) out[i] = make_float4(0.f, 0.f, 0.f, 0.f);
}

// ---------- fused overlap-add epilogue for one channel ----------
__device__ __forceinline__ void write_out(float* __restrict__ out, size_t base,
                                          const unsigned long long* acc,
                                          int lane, int l) {
    float f[W_DIM];
#pragma unroll
    for (int q = 0; q < 20; ++q) unpack2(acc[q], f[2 * q], f[2 * q + 1]);

    // segment l = frame[l][0:20] + frame[l-1][20:40] (prev frame via shuffle)
#pragma unroll
    for (int j = 0; j < STEP; ++j) {
        float up = __shfl_up_sync(0xffffffffu, f[STEP + j], 1);
        float lo = f[j];
        if (lane > 0)      out[base + j] = lo + up;          // complete value
        else if (l > 0)    atomicAdd(&out[base + j], lo);    // pairs with prev warp
        else               out[base + j] = lo;               // l==0: sole contributor
    }
    if (lane == 31) {
#pragma unroll
        for (int j = 0; j < STEP; ++j)
            atomicAdd(&out[base + STEP + j], f[STEP + j]);
    }
}

__global__ void __launch_bounds__(NT, 4)
decoder_kernel(const float* __restrict__ mix,
               const float* __restrict__ mask,
               const float* __restrict__ basis,
               float* __restrict__ out) {
    // basis transposed + packed f32x2 in shared: bsh2[e*10+q] = {b[2q..2q+3][e]}
    // 16B-aligned rows of 160B -> LDS.128 yields two u64 FFMA2 operands, no MOVs
    __shared__ ulonglong2 bsh2[E_DIM * 10];
    {
        unsigned long long* b64 = reinterpret_cast<unsigned long long*>(bsh2);
        for (int i = threadIdx.x; i < E_DIM * 20; i += NT) {
            int e = i / 20, p = i - e * 20;
            b64[i] = pack2(basis[(2 * p) * E_DIM + e], basis[(2 * p + 1) * E_DIM + e]);
        }
    }
    __syncthreads();

    const int item = blockIdx.x * NT + threadIdx.x;   // exactly B*L items
    const int b = item / L_DIM;
    const int l = item - b * L_DIM;
    const int lane = threadIdx.x & 31;

    const float* pm  = mix  + (size_t)b * E_DIM * L_DIM + l;
    const float* pk0 = mask + ((size_t)b * C_DIM + 0) * E_DIM * L_DIM + l;
    const float* pk1 = pk0 + (size_t)E_DIM * L_DIM;

    unsigned long long acc0[20], acc1[20];
#pragma unroll
    for (int i = 0; i < 20; ++i) { acc0[i] = 0ull; acc1[i] = 0ull; }

    // software pipeline: prefetch group 0
    float mA[EUNR], k0A[EUNR], k1A[EUNR];
#pragma unroll
    for (int u = 0; u < EUNR; ++u) mA[u]  = pm [(size_t)u * L_DIM];
#pragma unroll
    for (int u = 0; u < EUNR; ++u) k0A[u] = pk0[(size_t)u * L_DIM];
#pragma unroll
    for (int u = 0; u < EUNR; ++u) k1A[u] = pk1[(size_t)u * L_DIM];
    pm  += (size_t)EUNR * L_DIM;
    pk0 += (size_t)EUNR * L_DIM;
    pk1 += (size_t)EUNR * L_DIM;

#pragma unroll 1
    for (int e = 0; e < E_DIM; e += EUNR) {
        // prefetch next group (12 LDGs in flight under the FFMA2 burst below)
        float mB[EUNR], k0B[EUNR], k1B[EUNR];
        if (e + EUNR < E_DIM) {
#pragma unroll
            for (int u = 0; u < EUNR; ++u) mB[u]  = pm [(size_t)u * L_DIM];
#pragma unroll
            for (int u = 0; u < EUNR; ++u) k0B[u] = pk0[(size_t)u * L_DIM];
#pragma unroll
            for (int u = 0; u < EUNR; ++u) k1B[u] = pk1[(size_t)u * L_DIM];
            pm  += (size_t)EUNR * L_DIM;
            pk0 += (size_t)EUNR * L_DIM;
            pk1 += (size_t)EUNR * L_DIM;
        }

#pragma unroll
        for (int u = 0; u < EUNR; ++u) {
            float s0 = mA[u] * k0A[u];
            float s1 = mA[u] * k1A[u];
            unsigned long long s0d = pack2(s0, s0);
            unsigned long long s1d = pack2(s1, s1);

            const ulonglong2* brow = &bsh2[(e + u) * 10];
#pragma unroll
            for (int q = 0; q < 10; ++q) {
                ulonglong2 bv = brow[q];          // LDS.128 broadcast -> 2 u64 operands
                fma2(acc0[2 * q],     s0d, bv.x);
                fma2(acc0[2 * q + 1], s0d, bv.y);
                fma2(acc1[2 * q],     s1d, bv.x);
                fma2(acc1[2 * q + 1], s1d, bv.y);
            }
        }

#pragma unroll
        for (int u = 0; u < EUNR; ++u) { mA[u] = mB[u]; k0A[u] = k0B[u]; k1A[u] = k1B[u]; }
    }

    const size_t base0 = ((size_t)b * C_DIM + 0) * T_DIM + (size_t)l * STEP;
    const size_t base1 = base0 + T_DIM;
    write_out(out, base0, acc0, lane, l);
    write_out(out, base1, acc1, lane, l);
}

extern "C" void kernel_launch(void* const* d_in, const int* in_sizes, int n_in,
                              void* d_out, int out_size) {
    // Identify inputs by element count for robustness.
    const float *mix = nullptr, *mask = nullptr, *basis = nullptr;
    for (int i = 0; i < n_in; ++i) {
        long long s = in_sizes[i];
        if (s == (long long)B_DIM * E_DIM * L_DIM)              mix   = (const float*)d_in[i];
        else if (s == (long long)B_DIM * C_DIM * E_DIM * L_DIM) mask  = (const float*)d_in[i];
        else if (s == (long long)W_DIM * E_DIM)                 basis = (const float*)d_in[i];
    }
    float* out = (float*)d_out;

    int n4 = out_size / 4;
    zero_kernel<<<(n4 + 255) / 256, 256>>>((float4*)out, n4);

    decoder_kernel<<<(B_DIM * L_DIM) / NT, NT>>>(mix, mask, basis, out);
}

// round 6
// speedup vs baseline: 1.9863x; 1.5399x over previous
#include <cuda_runtime.h>
#include <stdint.h>

#define B_DIM 4
#define C_DIM 2
#define E_DIM 256
#define L_DIM 16000
#define W_DIM 40
#define STEP  20
#define T_DIM ((L_DIM - 1) * STEP + W_DIM)   // 320020
#define NT    128

#define KC      32          // e's per stage
#define NSTAGE  (E_DIM / KC)  // 8
#define PITCH_A 136         // uint32 pitch for sA rows (mod 32 == 8 -> conflict-free A frags)
#define PITCH_B 36          // uint32 pitch for sB rows (mod 32 == 4 -> conflict-free B frags)
#define PITCH_D 40          // float pitch for D tile

#define SA_WORDS (KC * PITCH_A)        // 4352
#define SB_WORDS (W_DIM * PITCH_B)     // 1440
#define SD_WORDS (NT * PITCH_D)        // 5120
// loop phase uses SA+SB; epilogue overlays SD on the same memory
#define SMEM_WORDS ((SA_WORDS + SB_WORDS) > SD_WORDS ? (SA_WORDS + SB_WORDS) : SD_WORDS)

__device__ __forceinline__ uint32_t f2tf32(float f) {
    uint32_t u;
    asm("cvt.rna.tf32.f32 %0, %1;" : "=r"(u) : "f"(f));
    return u;
}

__device__ __forceinline__ void mma_tf32(float* d, const uint32_t* a, const uint32_t* b) {
    asm volatile(
        "mma.sync.aligned.m16n8k8.row.col.f32.tf32.tf32.f32 "
        "{%0,%1,%2,%3}, {%4,%5,%6,%7}, {%8,%9}, {%0,%1,%2,%3};"
        : "+f"(d[0]), "+f"(d[1]), "+f"(d[2]), "+f"(d[3])
        : "r"(a[0]), "r"(a[1]), "r"(a[2]), "r"(a[3]), "r"(b[0]), "r"(b[1]));
}

// ---------- zero-init (d_out is poisoned; atomic targets need 0) ----------
__global__ void zero_kernel(float4* __restrict__ out, int n4) {
    int i = blockIdx.x * blockDim.x + threadIdx.x;
    if (i < n4) out[i] = make_float4(0.f, 0.f, 0.f, 0.f);
}

__global__ void __launch_bounds__(NT, 4)
decoder_kernel(const float* __restrict__ mix,
               const float* __restrict__ mask,
               const float* __restrict__ basis,
               float* __restrict__ out) {
    __shared__ __align__(16) uint32_t smem[SMEM_WORDS];
    uint32_t* sA = smem;                 // [KC][PITCH_A] tf32 bits: sA[e_loc][l]
    uint32_t* sB = smem + SA_WORDS;      // [W][PITCH_B]  tf32 bits: sB[w][e_loc]
    float*    sD = reinterpret_cast<float*>(smem);  // [128][PITCH_D] (epilogue overlay)

    const int tid   = threadIdx.x;
    const int wid   = tid >> 5;
    const int lane  = tid & 31;
    const int g     = lane >> 2;         // groupID
    const int tig   = lane & 3;          // thread-in-group

    const int bc    = blockIdx.x & 7;    // bc minor -> paired-c CTAs share mix in L2
    const int ltile = blockIdx.x >> 3;
    const int b     = bc >> 1;
    const int c     = bc & 1;
    const int l     = ltile * NT + tid;

    const float* pmix  = mix  + (size_t)b * E_DIM * L_DIM + (size_t)ltile * NT;
    const float* pmask = mask + ((size_t)b * C_DIM + c) * E_DIM * L_DIM + (size_t)ltile * NT;

    float acc[2][5][4];
#pragma unroll
    for (int mt = 0; mt < 2; ++mt)
#pragma unroll
        for (int nt = 0; nt < 5; ++nt)
#pragma unroll
            for (int r = 0; r < 4; ++r) acc[mt][nt][r] = 0.f;

    const int mbase = wid * 32;

#pragma unroll 1
    for (int st = 0; st < NSTAGE; ++st) {
        const int e0 = st * KC;
        __syncthreads();   // protect prior-stage frag reads before overwrite

        // ---- stage s = mix*mask into sA (tf32) ----
#pragma unroll
        for (int i = 0; i < 8; ++i) {
            int idx   = (i << 7) + tid;          // 0..1023
            int e_loc = idx >> 5;                // 0..31
            int l4    = idx & 31;                // 0..31
            const float4 mv = *reinterpret_cast<const float4*>(
                pmix + (size_t)(e0 + e_loc) * L_DIM + l4 * 4);
            const float4 kv = *reinterpret_cast<const float4*>(
                pmask + (size_t)(e0 + e_loc) * L_DIM + l4 * 4);
            uint4 sv;
            sv.x = f2tf32(mv.x * kv.x);
            sv.y = f2tf32(mv.y * kv.y);
            sv.z = f2tf32(mv.z * kv.z);
            sv.w = f2tf32(mv.w * kv.w);
            *reinterpret_cast<uint4*>(&sA[e_loc * PITCH_A + l4 * 4]) = sv;
        }

        // ---- stage basis chunk into sB (tf32): sB[w][e_loc] ----
#pragma unroll
        for (int i = 0; i < 3; ++i) {
            int idx = tid + (i << 7);            // 0..319 used
            if (idx < (W_DIM * KC) / 4) {
                int w  = idx >> 3;               // 0..39
                int e4 = idx & 7;                // 0..7
                const float4 bv = *reinterpret_cast<const float4*>(
                    basis + (size_t)w * E_DIM + e0 + e4 * 4);
                uint4 tv;
                tv.x = f2tf32(bv.x);
                tv.y = f2tf32(bv.y);
                tv.z = f2tf32(bv.z);
                tv.w = f2tf32(bv.w);
                *reinterpret_cast<uint4*>(&sB[w * PITCH_B + e4 * 4]) = tv;
            }
        }
        __syncthreads();

        // ---- 4 k-steps of m16n8k8 ----
#pragma unroll
        for (int ks = 0; ks < 4; ++ks) {
            const int kb = ks * 8;
            uint32_t a[2][4];
#pragma unroll
            for (int mt = 0; mt < 2; ++mt) {
                int m0 = mbase + mt * 16 + g;
                a[mt][0] = sA[(kb + tig) * PITCH_A + m0];
                a[mt][1] = sA[(kb + tig) * PITCH_A + m0 + 8];
                a[mt][2] = sA[(kb + tig + 4) * PITCH_A + m0];
                a[mt][3] = sA[(kb + tig + 4) * PITCH_A + m0 + 8];
            }
            uint32_t bf[5][2];
#pragma unroll
            for (int nt = 0; nt < 5; ++nt) {
                bf[nt][0] = sB[(nt * 8 + g) * PITCH_B + kb + tig];
                bf[nt][1] = sB[(nt * 8 + g) * PITCH_B + kb + tig + 4];
            }
#pragma unroll
            for (int mt = 0; mt < 2; ++mt)
#pragma unroll
                for (int nt = 0; nt < 5; ++nt)
                    mma_tf32(acc[mt][nt], a[mt], bf[nt]);
        }
    }

    // ---- write frags to D tile in SMEM (overlay) ----
    __syncthreads();
#pragma unroll
    for (int mt = 0; mt < 2; ++mt) {
#pragma unroll
        for (int nt = 0; nt < 5; ++nt) {
            int row = mbase + mt * 16 + g;
            int col = nt * 8 + 2 * tig;
            float2 lo = make_float2(acc[mt][nt][0], acc[mt][nt][1]);
            float2 hi = make_float2(acc[mt][nt][2], acc[mt][nt][3]);
            *reinterpret_cast<float2*>(&sD[row * PITCH_D + col])       = lo;
            *reinterpret_cast<float2*>(&sD[(row + 8) * PITCH_D + col]) = hi;
        }
    }
    __syncthreads();

    // ---- fused overlap-add epilogue (thread tid <-> l) ----
    float f[W_DIM];
#pragma unroll
    for (int q = 0; q < 10; ++q) {
        float4 v = *reinterpret_cast<float4*>(&sD[tid * PITCH_D + q * 4]);
        f[4 * q] = v.x; f[4 * q + 1] = v.y; f[4 * q + 2] = v.z; f[4 * q + 3] = v.w;
    }

    const size_t base = (size_t)bc * T_DIM + (size_t)l * STEP;
#pragma unroll
    for (int j = 0; j < STEP; ++j) {
        float up = __shfl_up_sync(0xffffffffu, f[STEP + j], 1);
        float lo = f[j];
        if (lane > 0)      out[base + j] = lo + up;          // complete value
        else if (l > 0)    atomicAdd(&out[base + j], lo);    // pairs with prev warp
        else               out[base + j] = lo;               // l==0: sole contributor
    }
    if (lane == 31) {
#pragma unroll
        for (int j = 0; j < STEP; ++j)
            atomicAdd(&out[base + STEP + j], f[STEP + j]);
    }
}

extern "C" void kernel_launch(void* const* d_in, const int* in_sizes, int n_in,
                              void* d_out, int out_size) {
    // Identify inputs by element count for robustness.
    const float *mix = nullptr, *mask = nullptr, *basis = nullptr;
    for (int i = 0; i < n_in; ++i) {
        long long s = in_sizes[i];
        if (s == (long long)B_DIM * E_DIM * L_DIM)              mix   = (const float*)d_in[i];
        else if (s == (long long)B_DIM * C_DIM * E_DIM * L_DIM) mask  = (const float*)d_in[i];
        else if (s == (long long)W_DIM * E_DIM)                 basis = (const float*)d_in[i];
    }
    float* out = (float*)d_out;

    int n4 = out_size / 4;
    zero_kernel<<<(n4 + 255) / 256, 256>>>((float4*)out, n4);

    decoder_kernel<<<B_DIM * C_DIM * (L_DIM / NT), NT>>>(mix, mask, basis, out);
}

// round 7
// speedup vs baseline: 2.2643x; 1.1400x over previous
#include <cuda_runtime.h>
#include <stdint.h>

#define B_DIM 4
#define C_DIM 2
#define E_DIM 256
#define L_DIM 16000
#define W_DIM 40
#define STEP  20
#define T_DIM ((L_DIM - 1) * STEP + W_DIM)   // 320020
#define NT    128

#define KC      16                 // e's per stage
#define NSTAGE  (E_DIM / KC)       // 16
#define PITCH_A 136                // mod 32 == 8 -> A frags conflict-free
#define PITCH_B 20                 // mod 32 == 20 -> B frags conflict-free (20g+tig distinct)
#define PITCH_D 40

#define SA_WORDS (KC * PITCH_A)    // 2176 per buffer
#define SB_WORDS (W_DIM * PITCH_B) // 800  per buffer
#define SD_WORDS (NT * PITCH_D)    // 5120
#define LOOP_WORDS (2 * (SA_WORDS + SB_WORDS))   // 5952
#define SMEM_WORDS (LOOP_WORDS > SD_WORDS ? LOOP_WORDS : SD_WORDS)

__device__ __forceinline__ uint32_t f2tf32(float f) {
    uint32_t u;
    asm("cvt.rna.tf32.f32 %0, %1;" : "=r"(u) : "f"(f));
    return u;
}

__device__ __forceinline__ void mma_tf32(float* d, const uint32_t* a, const uint32_t* b) {
    asm volatile(
        "mma.sync.aligned.m16n8k8.row.col.f32.tf32.tf32.f32 "
        "{%0,%1,%2,%3}, {%4,%5,%6,%7}, {%8,%9}, {%0,%1,%2,%3};"
        : "+f"(d[0]), "+f"(d[1]), "+f"(d[2]), "+f"(d[3])
        : "r"(a[0]), "r"(a[1]), "r"(a[2]), "r"(a[3]), "r"(b[0]), "r"(b[1]));
}

// ---------- zero-init (d_out is poisoned; atomic targets need 0) ----------
__global__ void zero_kernel(float4* __restrict__ out, int n4) {
    int i = blockIdx.x * blockDim.x + threadIdx.x;
    if (i < n4) out[i] = make_float4(0.f, 0.f, 0.f, 0.f);
}

__global__ void __launch_bounds__(NT, 4)
decoder_kernel(const float* __restrict__ mix,
               const float* __restrict__ mask,
               const float* __restrict__ basis,
               float* __restrict__ out) {
    __shared__ __align__(16) uint32_t smem[SMEM_WORDS];
    // double-buffered stage tiles
    uint32_t* sA[2] = { smem, smem + SA_WORDS };
    uint32_t* sB[2] = { smem + 2 * SA_WORDS, smem + 2 * SA_WORDS + SB_WORDS };
    float*    sD = reinterpret_cast<float*>(smem);   // epilogue overlay

    const int tid  = threadIdx.x;
    const int wid  = tid >> 5;
    const int lane = tid & 31;
    const int g    = lane >> 2;
    const int tig  = lane & 3;

    const int bc    = blockIdx.x & 7;      // bc minor -> paired-c CTAs share mix in L2
    const int ltile = blockIdx.x >> 3;
    const int b     = bc >> 1;
    const int c     = bc & 1;
    const int l     = ltile * NT + tid;

    const float* pmix  = mix  + (size_t)b * E_DIM * L_DIM + (size_t)ltile * NT;
    const float* pmask = mask + ((size_t)b * C_DIM + c) * E_DIM * L_DIM + (size_t)ltile * NT;

    // per-thread staging coords (fixed across stages)
    const int e_loc0 = tid >> 5;           // + 4*i gives e_loc for i-th quad
    const int l4     = (tid & 31) * 4;
    const int bw0    = tid >> 2;           // basis: w for idx=tid
    const int be0    = (tid & 3) * 4;
    const int bw1    = (128 + tid) >> 2;   // second basis quad (tid < 32)
    const int be1    = ((128 + tid) & 3) * 4;

    float acc[2][5][4];
#pragma unroll
    for (int mt = 0; mt < 2; ++mt)
#pragma unroll
        for (int nt = 0; nt < 5; ++nt)
#pragma unroll
            for (int r = 0; r < 4; ++r) acc[mt][nt][r] = 0.f;

    const int mbase = wid * 32;

    // ---- prefetch stage 0 into registers ----
    float4 mv[4], kv[4], bv0, bv1;
#pragma unroll
    for (int i = 0; i < 4; ++i) {
        mv[i] = *reinterpret_cast<const float4*>(pmix  + (size_t)(e_loc0 + 4 * i) * L_DIM + l4);
        kv[i] = *reinterpret_cast<const float4*>(pmask + (size_t)(e_loc0 + 4 * i) * L_DIM + l4);
    }
    bv0 = *reinterpret_cast<const float4*>(basis + (size_t)bw0 * E_DIM + be0);
    if (tid < 32) bv1 = *reinterpret_cast<const float4*>(basis + (size_t)bw1 * E_DIM + be1);

    // ---- store stage 0 ----
    {
        uint32_t* A = sA[0];
        uint32_t* Bs = sB[0];
#pragma unroll
        for (int i = 0; i < 4; ++i) {
            uint4 sv;
            sv.x = f2tf32(mv[i].x * kv[i].x);
            sv.y = f2tf32(mv[i].y * kv[i].y);
            sv.z = f2tf32(mv[i].z * kv[i].z);
            sv.w = f2tf32(mv[i].w * kv[i].w);
            *reinterpret_cast<uint4*>(&A[(e_loc0 + 4 * i) * PITCH_A + l4]) = sv;
        }
        {
            uint4 tv;
            tv.x = f2tf32(bv0.x); tv.y = f2tf32(bv0.y);
            tv.z = f2tf32(bv0.z); tv.w = f2tf32(bv0.w);
            *reinterpret_cast<uint4*>(&Bs[bw0 * PITCH_B + be0]) = tv;
        }
        if (tid < 32) {
            uint4 tv;
            tv.x = f2tf32(bv1.x); tv.y = f2tf32(bv1.y);
            tv.z = f2tf32(bv1.z); tv.w = f2tf32(bv1.w);
            *reinterpret_cast<uint4*>(&Bs[bw1 * PITCH_B + be1]) = tv;
        }
    }
    __syncthreads();

#pragma unroll 1
    for (int st = 0; st < NSTAGE; ++st) {
        const int cur = st & 1;

        // ---- prefetch stage st+1 (LDGs fly under the MMAs below) ----
        if (st + 1 < NSTAGE) {
            const size_t eoff = (size_t)(st + 1) * KC * L_DIM;
#pragma unroll
            for (int i = 0; i < 4; ++i) {
                mv[i] = *reinterpret_cast<const float4*>(pmix  + eoff + (size_t)(e_loc0 + 4 * i) * L_DIM + l4);
                kv[i] = *reinterpret_cast<const float4*>(pmask + eoff + (size_t)(e_loc0 + 4 * i) * L_DIM + l4);
            }
            const int e0n = (st + 1) * KC;
            bv0 = *reinterpret_cast<const float4*>(basis + (size_t)bw0 * E_DIM + e0n + be0);
            if (tid < 32) bv1 = *reinterpret_cast<const float4*>(basis + (size_t)bw1 * E_DIM + e0n + be1);
        }

        // ---- MMAs on current buffers ----
        const uint32_t* A = sA[cur];
        const uint32_t* Bs = sB[cur];
#pragma unroll
        for (int ks = 0; ks < 2; ++ks) {
            const int kb = ks * 8;
            uint32_t a[2][4];
#pragma unroll
            for (int mt = 0; mt < 2; ++mt) {
                int m0 = mbase + mt * 16 + g;
                a[mt][0] = A[(kb + tig) * PITCH_A + m0];
                a[mt][1] = A[(kb + tig) * PITCH_A + m0 + 8];
                a[mt][2] = A[(kb + tig + 4) * PITCH_A + m0];
                a[mt][3] = A[(kb + tig + 4) * PITCH_A + m0 + 8];
            }
            uint32_t bf[5][2];
#pragma unroll
            for (int nt = 0; nt < 5; ++nt) {
                bf[nt][0] = Bs[(nt * 8 + g) * PITCH_B + kb + tig];
                bf[nt][1] = Bs[(nt * 8 + g) * PITCH_B + kb + tig + 4];
            }
#pragma unroll
            for (int mt = 0; mt < 2; ++mt)
#pragma unroll
                for (int nt = 0; nt < 5; ++nt)
                    mma_tf32(acc[mt][nt], a[mt], bf[nt]);
        }

        // ---- store stage st+1 into the other buffer ----
        if (st + 1 < NSTAGE) {
            uint32_t* An = sA[cur ^ 1];
            uint32_t* Bn = sB[cur ^ 1];
#pragma unroll
            for (int i = 0; i < 4; ++i) {
                uint4 sv;
                sv.x = f2tf32(mv[i].x * kv[i].x);
                sv.y = f2tf32(mv[i].y * kv[i].y);
                sv.z = f2tf32(mv[i].z * kv[i].z);
                sv.w = f2tf32(mv[i].w * kv[i].w);
                *reinterpret_cast<uint4*>(&An[(e_loc0 + 4 * i) * PITCH_A + l4]) = sv;
            }
            {
                uint4 tv;
                tv.x = f2tf32(bv0.x); tv.y = f2tf32(bv0.y);
                tv.z = f2tf32(bv0.z); tv.w = f2tf32(bv0.w);
                *reinterpret_cast<uint4*>(&Bn[bw0 * PITCH_B + be0]) = tv;
            }
            if (tid < 32) {
                uint4 tv;
                tv.x = f2tf32(bv1.x); tv.y = f2tf32(bv1.y);
                tv.z = f2tf32(bv1.z); tv.w = f2tf32(bv1.w);
                *reinterpret_cast<uint4*>(&Bn[bw1 * PITCH_B + be1]) = tv;
            }
        }
        __syncthreads();
    }

    // ---- write frags to D tile in SMEM (overlay; loop buffers dead now) ----
#pragma unroll
    for (int mt = 0; mt < 2; ++mt) {
#pragma unroll
        for (int nt = 0; nt < 5; ++nt) {
            int row = mbase + mt * 16 + g;
            int col = nt * 8 + 2 * tig;
            *reinterpret_cast<float2*>(&sD[row * PITCH_D + col]) =
                make_float2(acc[mt][nt][0], acc[mt][nt][1]);
            *reinterpret_cast<float2*>(&sD[(row + 8) * PITCH_D + col]) =
                make_float2(acc[mt][nt][2], acc[mt][nt][3]);
        }
    }
    __syncthreads();

    // ---- fused overlap-add epilogue (thread tid <-> l) ----
    float f[W_DIM];
#pragma unroll
    for (int q = 0; q < 10; ++q) {
        float4 v = *reinterpret_cast<float4*>(&sD[tid * PITCH_D + q * 4]);
        f[4 * q] = v.x; f[4 * q + 1] = v.y; f[4 * q + 2] = v.z; f[4 * q + 3] = v.w;
    }

    const size_t base = (size_t)bc * T_DIM + (size_t)l * STEP;
#pragma unroll
    for (int j = 0; j < STEP; ++j) {
        float up = __shfl_up_sync(0xffffffffu, f[STEP + j], 1);
        float lo = f[j];
        if (lane > 0)      out[base + j] = lo + up;          // complete value
        else if (l > 0)    atomicAdd(&out[base + j], lo);    // pairs with prev warp
        else               out[base + j] = lo;               // l==0: sole contributor
    }
    if (lane == 31) {
#pragma unroll
        for (int j = 0; j < STEP; ++j)
            atomicAdd(&out[base + STEP + j], f[STEP + j]);
    }
}

extern "C" void kernel_launch(void* const* d_in, const int* in_sizes, int n_in,
                              void* d_out, int out_size) {
    // Identify inputs by element count for robustness.
    const float *mix = nullptr, *mask = nullptr, *basis = nullptr;
    for (int i = 0; i < n_in; ++i) {
        long long s = in_sizes[i];
        if (s == (long long)B_DIM * E_DIM * L_DIM)              mix   = (const float*)d_in[i];
        else if (s == (long long)B_DIM * C_DIM * E_DIM * L_DIM) mask  = (const float*)d_in[i];
        else if (s == (long long)W_DIM * E_DIM)                 basis = (const float*)d_in[i];
    }
    float* out = (float*)d_out;

    int n4 = out_size / 4;
    zero_kernel<<<(n4 + 255) / 256, 256>>>((float4*)out, n4);

    decoder_kernel<<<B_DIM * C_DIM * (L_DIM / NT), NT>>>(mix, mask, basis, out);
}

// round 8
// speedup vs baseline: 2.4084x; 1.0636x over previous
#include <cuda_runtime.h>
#include <stdint.h>

#define B_DIM 4
#define C_DIM 2
#define E_DIM 256
#define L_DIM 16000
#define W_DIM 40
#define STEP  20
#define T_DIM ((L_DIM - 1) * STEP + W_DIM)   // 320020
#define NT    128

#define KC      16
#define NSTAGE  (E_DIM / KC)       // 16
#define NBUF    3
#define PITCH_A 136                // words; mod 32 == 8 -> conflict-free frag reads
#define PITCH_B 20                 // words; 20g+tig distinct mod 32
#define PITCH_D 40

#define SA_WORDS (KC * PITCH_A)        // 2176 per buffer (per array)
#define SB_WORDS (W_DIM * PITCH_B)     // 800 per buffer
#define MIX_OFF  0
#define MSK_OFF  (NBUF * SA_WORDS)                 // 6528
#define BAS_OFF  (2 * NBUF * SA_WORDS)             // 13056
#define LOOP_WORDS (2 * NBUF * SA_WORDS + NBUF * SB_WORDS)   // 15456
#define SD_WORDS (NT * PITCH_D)                    // 5120
#define SMEM_BYTES (LOOP_WORDS * 4)                // 61824 (> SD overlay)

__device__ __forceinline__ uint32_t f2tf32(float f) {
    uint32_t u;
    asm("cvt.rna.tf32.f32 %0, %1;" : "=r"(u) : "f"(f));
    return u;
}
__device__ __forceinline__ void mma_tf32(float* d, const uint32_t* a, const uint32_t* b) {
    asm volatile(
        "mma.sync.aligned.m16n8k8.row.col.f32.tf32.tf32.f32 "
        "{%0,%1,%2,%3}, {%4,%5,%6,%7}, {%8,%9}, {%0,%1,%2,%3};"
        : "+f"(d[0]), "+f"(d[1]), "+f"(d[2]), "+f"(d[3])
        : "r"(a[0]), "r"(a[1]), "r"(a[2]), "r"(a[3]), "r"(b[0]), "r"(b[1]));
}
__device__ __forceinline__ void cp16(uint32_t dst_smem, const void* src) {
    asm volatile("cp.async.cg.shared.global [%0], [%1], 16;" :: "r"(dst_smem), "l"(src));
}
__device__ __forceinline__ void cp_commit() {
    asm volatile("cp.async.commit_group;" ::: "memory");
}
__device__ __forceinline__ void cp_wait2() {
    asm volatile("cp.async.wait_group 2;" ::: "memory");
}

// ---------- zero-init (d_out is poisoned; atomic targets need 0) ----------
__global__ void zero_kernel(float4* __restrict__ out, int n4) {
    int i = blockIdx.x * blockDim.x + threadIdx.x;
    if (i < n4) out[i] = make_float4(0.f, 0.f, 0.f, 0.f);
}

__global__ void __launch_bounds__(NT, 3)
decoder_kernel(const float* __restrict__ mix,
               const float* __restrict__ mask,
               const float* __restrict__ basis,
               float* __restrict__ out) {
    extern __shared__ __align__(16) uint32_t smem[];
    const uint32_t smem_base = (uint32_t)__cvta_generic_to_shared(smem);
    float* sF = reinterpret_cast<float*>(smem);
    float* sD = sF;                                  // epilogue overlay

    const int tid  = threadIdx.x;
    const int wid  = tid >> 5;
    const int lane = tid & 31;
    const int g    = lane >> 2;
    const int tig  = lane & 3;

    const int bc    = blockIdx.x & 7;      // bc minor -> paired-c CTAs share mix in L2
    const int ltile = blockIdx.x >> 3;
    const int b     = bc >> 1;
    const int c     = bc & 1;
    const int l     = ltile * NT + tid;

    const float* pmix  = mix  + (size_t)b * E_DIM * L_DIM + (size_t)ltile * NT;
    const float* pmask = mask + ((size_t)b * C_DIM + c) * E_DIM * L_DIM + (size_t)ltile * NT;

    // staging coords (fixed): thread covers e rows e0+4i, columns l4..l4+3
    const int e0 = tid >> 5;
    const int l4 = (tid & 31) * 4;
    const int bw0 = tid >> 2;              // basis quad 0: w
    const int be0 = (tid & 3) * 4;         //               e offset
    const int bw1 = 32 + (tid >> 2);       // basis quad 1 (tid<32 only)

    float acc[2][5][4];
#pragma unroll
    for (int mt = 0; mt < 2; ++mt)
#pragma unroll
        for (int nt = 0; nt < 5; ++nt)
#pragma unroll
            for (int r = 0; r < 4; ++r) acc[mt][nt][r] = 0.f;

    const int mbase = wid * 32;

    // ---- stage issuer (cp.async, no registers) ----
    auto issue_stage = [&](int s) {
        if (s < NSTAGE) {
            const int buf = s % NBUF;
            const size_t eoff = (size_t)s * KC * L_DIM;
            const uint32_t dmix = smem_base + (MIX_OFF + buf * SA_WORDS) * 4;
            const uint32_t dmsk = smem_base + (MSK_OFF + buf * SA_WORDS) * 4;
#pragma unroll
            for (int i = 0; i < 4; ++i) {
                const int e = e0 + 4 * i;
                const uint32_t doff = (uint32_t)(e * PITCH_A + l4) * 4;
                cp16(dmix + doff, pmix  + eoff + (size_t)e * L_DIM + l4);
                cp16(dmsk + doff, pmask + eoff + (size_t)e * L_DIM + l4);
            }
            const uint32_t dbas = smem_base + (BAS_OFF + buf * SB_WORDS) * 4;
            cp16(dbas + (uint32_t)(bw0 * PITCH_B + be0) * 4,
                 basis + (size_t)bw0 * E_DIM + s * KC + be0);
            if (tid < 32)
                cp16(dbas + (uint32_t)(bw1 * PITCH_B + be0) * 4,
                     basis + (size_t)bw1 * E_DIM + s * KC + be0);
        }
        cp_commit();   // empty group past the end keeps the wait count uniform
    };

    // prologue: stages 0 and 1 in flight
    issue_stage(0);
    issue_stage(1);

#pragma unroll 1
    for (int st = 0; st < NSTAGE; ++st) {
        __syncthreads();            // all warps done with MMA(st-1) -> buf reusable
        issue_stage(st + 2);        // streams under the MMAs below
        cp_wait2();                 // my groups for stage st landed
        __syncthreads();            // everyone's stage-st data visible

        const int buf = st % NBUF;
        const float* fMix = sF + MIX_OFF + buf * SA_WORDS;
        const float* fMsk = sF + MSK_OFF + buf * SA_WORDS;
        const float* fB   = sF + BAS_OFF + buf * SB_WORDS;

#pragma unroll
        for (int ks = 0; ks < 2; ++ks) {
            const int kb = ks * 8;
            const int r1 = (kb + tig) * PITCH_A;
            const int r2 = (kb + tig + 4) * PITCH_A;
            uint32_t a[2][4];
#pragma unroll
            for (int mt = 0; mt < 2; ++mt) {
                const int m0 = mbase + mt * 16 + g;
                a[mt][0] = f2tf32(fMix[r1 + m0]     * fMsk[r1 + m0]);
                a[mt][1] = f2tf32(fMix[r1 + m0 + 8] * fMsk[r1 + m0 + 8]);
                a[mt][2] = f2tf32(fMix[r2 + m0]     * fMsk[r2 + m0]);
                a[mt][3] = f2tf32(fMix[r2 + m0 + 8] * fMsk[r2 + m0 + 8]);
            }
            uint32_t bf[5][2];
#pragma unroll
            for (int nt = 0; nt < 5; ++nt) {
                bf[nt][0] = f2tf32(fB[(nt * 8 + g) * PITCH_B + kb + tig]);
                bf[nt][1] = f2tf32(fB[(nt * 8 + g) * PITCH_B + kb + tig + 4]);
            }
#pragma unroll
            for (int mt = 0; mt < 2; ++mt)
#pragma unroll
                for (int nt = 0; nt < 5; ++nt)
                    mma_tf32(acc[mt][nt], a[mt], bf[nt]);
        }
    }

    // ---- write frags to D tile in SMEM (overlay; loop buffers dead) ----
    __syncthreads();
#pragma unroll
    for (int mt = 0; mt < 2; ++mt) {
#pragma unroll
        for (int nt = 0; nt < 5; ++nt) {
            int row = mbase + mt * 16 + g;
            int col = nt * 8 + 2 * tig;
            *reinterpret_cast<float2*>(&sD[row * PITCH_D + col]) =
                make_float2(acc[mt][nt][0], acc[mt][nt][1]);
            *reinterpret_cast<float2*>(&sD[(row + 8) * PITCH_D + col]) =
                make_float2(acc[mt][nt][2], acc[mt][nt][3]);
        }
    }
    __syncthreads();

    // ---- fused overlap-add epilogue (thread tid <-> l) ----
    float f[W_DIM];
#pragma unroll
    for (int q = 0; q < 10; ++q) {
        float4 v = *reinterpret_cast<float4*>(&sD[tid * PITCH_D + q * 4]);
        f[4 * q] = v.x; f[4 * q + 1] = v.y; f[4 * q + 2] = v.z; f[4 * q + 3] = v.w;
    }

    const size_t base = (size_t)bc * T_DIM + (size_t)l * STEP;
#pragma unroll
    for (int j = 0; j < STEP; ++j) {
        float up = __shfl_up_sync(0xffffffffu, f[STEP + j], 1);
        float lo = f[j];
        if (lane > 0)      out[base + j] = lo + up;          // complete value
        else if (l > 0)    atomicAdd(&out[base + j], lo);    // pairs with prev warp
        else               out[base + j] = lo;               // l==0: sole contributor
    }
    if (lane == 31) {
#pragma unroll
        for (int j = 0; j < STEP; ++j)
            atomicAdd(&out[base + STEP + j], f[STEP + j]);
    }
}

extern "C" void kernel_launch(void* const* d_in, const int* in_sizes, int n_in,
                              void* d_out, int out_size) {
    // Identify inputs by element count for robustness.
    const float *mix = nullptr, *mask = nullptr, *basis = nullptr;
    for (int i = 0; i < n_in; ++i) {
        long long s = in_sizes[i];
        if (s == (long long)B_DIM * E_DIM * L_DIM)              mix   = (const float*)d_in[i];
        else if (s == (long long)B_DIM * C_DIM * E_DIM * L_DIM) mask  = (const float*)d_in[i];
        else if (s == (long long)W_DIM * E_DIM)                 basis = (const float*)d_in[i];
    }
    float* out = (float*)d_out;

    int n4 = out_size / 4;
    zero_kernel<<<(n4 + 255) / 256, 256>>>((float4*)out, n4);

    cudaFuncSetAttribute(decoder_kernel,
                         cudaFuncAttributeMaxDynamicSharedMemorySize, SMEM_BYTES);
    decoder_kernel<<<B_DIM * C_DIM * (L_DIM / NT), NT, SMEM_BYTES>>>(mix, mask, basis, out);
}